// round 12
// baseline (speedup 1.0000x reference)
#include <cuda_runtime.h>
#include <cuda_fp16.h>
#include <math.h>
#include <stdint.h>

#define UNITS 1024
#define NB    32
#define NT    2048
#define M_TOTAL (NB * NT)

#define M_TILE 128
#define N_CHUNK 128
#define BK 32
#define N_CHUNKS (UNITS / N_CHUNK)   // 8
#define K_TILES  (UNITS / BK)        // 32
#define N_ITEMS  ((M_TOTAL / M_TILE) * N_CHUNKS)   // 4096
#define GRID_P   296                 // 2 CTAs per SM
#define PADH 8
#define ROWH (BK + PADH)             // 40 halves
#define ROWB (ROWH * 2)              // 80 bytes

// smem: 3 stages of (A:128x80B=10240, B:128x80B=10240)
#define STG    20480
#define S_A(s) ((s) * STG)
#define S_B(s) ((s) * STG + 10240)
#define S_CS   61440
#define S_VS   65536
#define S_RED  69632                 // float[4][128] = 2KB
#define S_TOTAL 71680

// ---- scratch (allocation-free rule: __device__ globals) ----
__device__ __half g_xh[(size_t)M_TOTAL * UNITS];  // x in fp16
__device__ __half g_w1h[UNITS * UNITS];           // W1 in fp16
__device__ float  g_c[NB * UNITS];
__device__ float  g_spart[N_CHUNKS][NB * NT];     // per-chunk score partials
#define CTX_SPLIT 8
__device__ float  g_ctxp[CTX_SPLIT * NB * UNITS];

__device__ __forceinline__ uint32_t sptr(const void* p) {
    return (uint32_t)__cvta_generic_to_shared(p);
}
#define LDMX4(r0, r1, r2, r3, a) \
    asm volatile("ldmatrix.sync.aligned.m8n8.x4.shared.b16 {%0,%1,%2,%3}, [%4];" \
                 : "=r"(r0), "=r"(r1), "=r"(r2), "=r"(r3) : "r"(a))
#define CP16(dst, src) \
    asm volatile("cp.async.cg.shared.global [%0], [%1], 16;" \
                 :: "r"(dst), "l"(src))
#define CP_COMMIT() asm volatile("cp.async.commit_group;" ::: "memory")
#define CP_WAIT1()  asm volatile("cp.async.wait_group 1;" ::: "memory")
#define CP_WAIT0()  asm volatile("cp.async.wait_group 0;" ::: "memory")

__device__ __forceinline__ void mma_f16(float d[4], const uint32_t a[4],
                                        const uint32_t b0, const uint32_t b1) {
    asm volatile(
        "mma.sync.aligned.m16n8k16.row.col.f32.f16.f16.f32 "
        "{%0,%1,%2,%3}, {%4,%5,%6,%7}, {%8,%9}, {%0,%1,%2,%3};"
        : "+f"(d[0]), "+f"(d[1]), "+f"(d[2]), "+f"(d[3])
        : "r"(a[0]), "r"(a[1]), "r"(a[2]), "r"(a[3]), "r"(b0), "r"(b1));
}

// ==================== converters: fp32 -> fp16 (one-off) ====================
__device__ __forceinline__ uint2 pack4(float4 v) {
    __half2 lo = __floats2half2_rn(v.x, v.y);
    __half2 hi = __floats2half2_rn(v.z, v.w);
    uint2 r;
    r.x = *(uint32_t*)&lo;
    r.y = *(uint32_t*)&hi;
    return r;
}
__global__ void convert_x_kernel(const float* __restrict__ x) {
    const size_t i = ((size_t)blockIdx.x * 256 + threadIdx.x) * 8;
    const float4 v0 = *(const float4*)(x + i);
    const float4 v1 = *(const float4*)(x + i + 4);
    uint2 a = pack4(v0), b = pack4(v1);
    *(uint4*)(g_xh + i) = make_uint4(a.x, a.y, b.x, b.y);
}
__global__ void convert_w1_kernel(const float* __restrict__ w) {
    const size_t i = ((size_t)blockIdx.x * 256 + threadIdx.x) * 8;
    const float4 v0 = *(const float4*)(w + i);
    const float4 v1 = *(const float4*)(w + i + 4);
    uint2 a = pack4(v0), b = pack4(v1);
    *(uint4*)(g_w1h + i) = make_uint4(a.x, a.y, b.x, b.y);
}

// ============================ Kernel A: c[b][v] ============================
__global__ void bias_hidden_kernel(const float* __restrict__ hidden,
                                   const float* __restrict__ W2_w,
                                   const float* __restrict__ W1_b,
                                   const float* __restrict__ W2_b) {
    __shared__ float hs[UNITS];
    const int b = blockIdx.x;
    for (int u = threadIdx.x; u < UNITS; u += 256)
        hs[u] = hidden[b * UNITS + u];
    __syncthreads();
    const int warp = threadIdx.x >> 5, lane = threadIdx.x & 31;
    const int v0 = blockIdx.y * 128;
    for (int v = v0 + warp; v < v0 + 128; v += 8) {
        const float* wr = W2_w + (size_t)v * UNITS;
        float s = 0.f;
        #pragma unroll 8
        for (int u = lane; u < UNITS; u += 32) s += hs[u] * wr[u];
        #pragma unroll
        for (int m = 16; m; m >>= 1) s += __shfl_xor_sync(0xffffffffu, s, m);
        if (lane == 0) g_c[b * UNITS + v] = s + W1_b[v] + W2_b[v];
    }
}

// == Kernel B: persistent fp16 mma GEMM, 2 CTAs/SM, (m,nc) work items =======
// 296 CTAs x 256 threads (8 warps = 2m x 4n, warp tile 64x32).
// CTA tile 128x128, BK=32, 3-stage cp.async. 4096 items round-robin.
__global__ void __launch_bounds__(256, 2) score_kernel(
    const float* __restrict__ Vw) {
    extern __shared__ char smem[];
    const uint32_t sb = sptr(smem);

    const int tid  = threadIdx.x;
    const int wid  = tid >> 5, lane = tid & 31;
    const int wm   = wid >> 2;          // 0..1  rows wm*64
    const int wn   = wid & 3;           // 0..3  cols wn*32
    const int grp  = lane >> 2;
    const int thr  = lane & 3;

    float* cs = (float*)(smem + S_CS);
    float* vs = (float*)(smem + S_VS);
    for (int i = tid; i < UNITS; i += 256)
        vs[i] = Vw[i];

    // cp.async mapping (BK=32, 256 thr): A 512 uint4 -> 2/thr; B 512 -> 2/thr
    const int lrow = tid >> 2;          // 0..63, +j*64
    const int lseg = tid & 3;           // uint4 within 64B row

    // ldmatrix fragment bases (stage offset added in-loop)
    const uint32_t aF = sb + (uint32_t)((wm * 64 + (lane & 15)) * ROWB
                                        + (lane >> 4) * 16);
    const uint32_t bF = sb + 10240u
        + (uint32_t)((wn * 32 + ((lane >> 4) << 3) + (lane & 7)) * ROWB
                     + ((lane >> 3) & 1) * 16);

    float (*sred)[M_TILE] = (float(*)[M_TILE])(smem + S_RED);

    for (int item = blockIdx.x; item < N_ITEMS; item += GRID_P) {
        const int m_idx = item >> 3;
        const int nc    = item & 7;
        const int m0    = m_idx * M_TILE;
        const int b     = m0 / NT;
        const int n0    = nc * N_CHUNK;
        const __half* xg = g_xh  + (size_t)m0 * UNITS;
        const __half* wg = g_w1h + (size_t)n0 * UNITS;

        float d[4][4][4];
        #pragma unroll
        for (int mf = 0; mf < 4; ++mf)
            #pragma unroll
            for (int nf = 0; nf < 4; ++nf)
                #pragma unroll
                for (int q = 0; q < 4; ++q) d[mf][nf][q] = 0.f;

        // --- async tile fill: stage s <- k-tile kt ---
        #define FILL_TILE(s, kt) do {                                          \
            const uint32_t as = sb + S_A(s);                                   \
            const uint32_t bs = sb + S_B(s);                                   \
            const int kbase = (kt) * BK;                                       \
            _Pragma("unroll")                                                  \
            for (int j = 0; j < 2; ++j) {                                      \
                const int r = lrow + j * 64;                                   \
                CP16(as + r * ROWB + lseg * 16,                                \
                     xg + (size_t)r * UNITS + kbase + lseg * 8);               \
                CP16(bs + r * ROWB + lseg * 16,                                \
                     wg + (size_t)r * UNITS + kbase + lseg * 8);               \
            }                                                                  \
            CP_COMMIT();                                                       \
        } while (0)

        FILL_TILE(0, 0);
        FILL_TILE(1, 1);

        // per-item bias vector (safe: prev item's reads ended before its
        // last __syncthreads)
        for (int i = tid; i < UNITS; i += 256)
            cs[i] = g_c[b * UNITS + i];

        int stage = 0;
        for (int kt = 0; kt < K_TILES; ++kt) {
            if (kt + 1 < K_TILES) { CP_WAIT1(); } else { CP_WAIT0(); }
            __syncthreads();       // tile kt ready (and cs visible)

            if (kt + 2 < K_TILES) {
                const int ns = (stage + 2 >= 3) ? stage - 1 : stage + 2;
                FILL_TILE(ns, kt + 2);
            }

            const uint32_t abuf = aF + (uint32_t)(stage * STG);
            const uint32_t bbuf = bF + (uint32_t)(stage * STG);
            #pragma unroll
            for (int ks = 0; ks < 2; ++ks) {
                const uint32_t koff = ks * 32;
                uint32_t af[4][4];
                #pragma unroll
                for (int mf = 0; mf < 4; ++mf)
                    LDMX4(af[mf][0], af[mf][1], af[mf][2], af[mf][3],
                          abuf + mf * 16 * ROWB + koff);
                uint32_t bb[2][4];
                #pragma unroll
                for (int nfp = 0; nfp < 2; ++nfp)
                    LDMX4(bb[nfp][0], bb[nfp][1], bb[nfp][2], bb[nfp][3],
                          bbuf + nfp * 16 * ROWB + koff);
                #pragma unroll
                for (int nfp = 0; nfp < 2; ++nfp) {
                    #pragma unroll
                    for (int mf = 0; mf < 4; ++mf) {
                        mma_f16(d[mf][nfp * 2 + 0], af[mf], bb[nfp][0], bb[nfp][1]);
                        mma_f16(d[mf][nfp * 2 + 1], af[mf], bb[nfp][2], bb[nfp][3]);
                    }
                }
            }
            stage = (stage == 2) ? 0 : stage + 1;
        }
        #undef FILL_TILE

        // Epilogue: tanh + V-weighted reduce (partial over this n-chunk)
        float sacc[4][2];
        #pragma unroll
        for (int mf = 0; mf < 4; ++mf) {
            sacc[mf][0] = 0.f; sacc[mf][1] = 0.f;
            #pragma unroll
            for (int nf = 0; nf < 4; ++nf) {
                const int n = n0 + wn * 32 + nf * 8 + 2 * thr;
                sacc[mf][0] += tanhf(d[mf][nf][0] + cs[n])     * vs[n];
                sacc[mf][0] += tanhf(d[mf][nf][1] + cs[n + 1]) * vs[n + 1];
                sacc[mf][1] += tanhf(d[mf][nf][2] + cs[n])     * vs[n];
                sacc[mf][1] += tanhf(d[mf][nf][3] + cs[n + 1]) * vs[n + 1];
            }
        }

        __syncthreads();    // all ldmatrix done; sred buffer free
        #pragma unroll
        for (int mf = 0; mf < 4; ++mf) {
            #pragma unroll
            for (int h = 0; h < 2; ++h) {
                float v = sacc[mf][h];
                v += __shfl_xor_sync(0xffffffffu, v, 1);
                v += __shfl_xor_sync(0xffffffffu, v, 2);
                if (thr == 0)
                    sred[wn][wm * 64 + mf * 16 + h * 8 + grp] = v;
            }
        }
        __syncthreads();
        if (tid < M_TILE) {
            float s = (sred[0][tid] + sred[1][tid])
                    + (sred[2][tid] + sred[3][tid]);
            g_spart[nc][m0 + tid] = s;
        }
        __syncthreads();    // sred reads done before next item reuses smem
    }
}

// ============ Kernel C: softmax per batch (sums 8 chunk partials) ==========
__global__ void softmax_kernel(float* __restrict__ out_w) {
    __shared__ float s[NT];
    __shared__ float red[32];
    const int b = blockIdx.x;
    const int tid = threadIdx.x;
    const int lane = tid & 31, warp = tid >> 5;

    float lmax = -INFINITY;
    for (int t = tid; t < NT; t += 256) {
        const int i = b * NT + t;
        float v = 0.f;
        #pragma unroll
        for (int p = 0; p < N_CHUNKS; ++p) v += g_spart[p][i];
        s[t] = v;
        lmax = fmaxf(lmax, v);
    }
    #pragma unroll
    for (int m = 16; m; m >>= 1)
        lmax = fmaxf(lmax, __shfl_xor_sync(0xffffffffu, lmax, m));
    if (lane == 0) red[warp] = lmax;
    __syncthreads();
    float bmax = red[0];
    #pragma unroll
    for (int w = 1; w < 8; w++) bmax = fmaxf(bmax, red[w]);

    float lsum = 0.f;
    for (int t = tid; t < NT; t += 256) {
        const float e = __expf(s[t] - bmax);
        s[t] = e;
        lsum += e;
    }
    #pragma unroll
    for (int m = 16; m; m >>= 1)
        lsum += __shfl_xor_sync(0xffffffffu, lsum, m);
    __syncthreads();
    if (lane == 0) red[warp] = lsum;
    __syncthreads();
    float bsum = 0.f;
    #pragma unroll
    for (int w = 0; w < 8; w++) bsum += red[w];
    const float inv = 1.f / bsum;
    for (int t = tid; t < NT; t += 256)
        out_w[b * NT + t] = s[t] * inv;
}

// ====== Kernel D: context partials (8-way t-split, fp16 x) =================
__global__ void __launch_bounds__(256) context_part_kernel(
    const float* __restrict__ w) {
    __shared__ float ws[NT / CTX_SPLIT];    // 256
    const int b  = blockIdx.x;
    const int uc = blockIdx.y;
    const int tc = blockIdx.z;
    const int t0 = tc * (NT / CTX_SPLIT);
    ws[threadIdx.x] = w[b * NT + t0 + threadIdx.x];
    __syncthreads();
    const int u = uc * 256 + threadIdx.x;
    const __half* xp = g_xh + (size_t)b * NT * UNITS + (size_t)t0 * UNITS + u;
    float a0 = 0.f, a1 = 0.f, a2 = 0.f, a3 = 0.f;
    for (int t = 0; t < NT / CTX_SPLIT; t += 4) {
        a0 += ws[t + 0] * __half2float(xp[(size_t)(t + 0) * UNITS]);
        a1 += ws[t + 1] * __half2float(xp[(size_t)(t + 1) * UNITS]);
        a2 += ws[t + 2] * __half2float(xp[(size_t)(t + 2) * UNITS]);
        a3 += ws[t + 3] * __half2float(xp[(size_t)(t + 3) * UNITS]);
    }
    g_ctxp[(size_t)tc * NB * UNITS + b * UNITS + u] = (a0 + a1) + (a2 + a3);
}

__global__ void context_reduce_kernel(float* __restrict__ out_ctx) {
    const int i = blockIdx.x * 256 + threadIdx.x;
    float s = 0.f;
    #pragma unroll
    for (int p = 0; p < CTX_SPLIT; ++p)
        s += g_ctxp[(size_t)p * NB * UNITS + i];
    out_ctx[i] = s;
}

// ---------------------------------------------------------------------------
extern "C" void kernel_launch(void* const* d_in, const int* in_sizes, int n_in,
                              void* d_out, int out_size) {
    const float* x      = (const float*)d_in[0];
    const float* hidden = (const float*)d_in[1];
    const float* W1_w   = (const float*)d_in[2];
    const float* W1_b   = (const float*)d_in[3];
    const float* W2_w   = (const float*)d_in[4];
    const float* W2_b   = (const float*)d_in[5];
    const float* V_w    = (const float*)d_in[6];
    // d_in[7] = V_b: softmax-invariant, unused.

    float* out     = (float*)d_out;
    float* out_ctx = out;                   // 32*1024
    float* out_w   = out + NB * UNITS;      // 32*2048

    cudaFuncSetAttribute(score_kernel,
                         cudaFuncAttributeMaxDynamicSharedMemorySize, S_TOTAL);

    convert_x_kernel<<<(int)((size_t)M_TOTAL * UNITS / (256 * 8)), 256>>>(x);
    convert_w1_kernel<<<UNITS * UNITS / (256 * 8), 256>>>(W1_w);
    bias_hidden_kernel<<<dim3(NB, 8), 256>>>(hidden, W2_w, W1_b, W2_b);
    score_kernel<<<GRID_P, 256, S_TOTAL>>>(V_w);
    softmax_kernel<<<NB, 256>>>(out_w);
    context_part_kernel<<<dim3(NB, 4, CTX_SPLIT), 256>>>(out_w);
    context_reduce_kernel<<<NB * UNITS / 256, 256>>>(out_ctx);
}

// round 13
// speedup vs baseline: 1.1038x; 1.1038x over previous
#include <cuda_runtime.h>
#include <cuda_fp16.h>
#include <math.h>
#include <stdint.h>

#define UNITS 1024
#define NB    32
#define NT    2048
#define M_TOTAL (NB * NT)

#define M_TILE 128
#define N_CHUNK 256
#define BK 64
#define N_CHUNKS (UNITS / N_CHUNK)   // 4
#define K_TILES  (UNITS / BK)        // 16
#define N_ITEMS  ((M_TOTAL / M_TILE) * N_CHUNKS)   // 2048
#define GRID_P   148
#define PADH 8
#define ROWH (BK + PADH)             // 72 halves
#define ROWB (ROWH * 2)              // 144 bytes

// smem: 3 stages of (A:128x144B=18432, B:256x144B=36864)
#define STG    55296
#define S_A(s) ((s) * STG)
#define S_B(s) ((s) * STG + 18432)
#define S_VS   165888
#define S_RED  169984                // float[8][128] = 4KB
#define S_TOTAL 174080

// ---- scratch (allocation-free rule: __device__ globals) ----
__device__ __half g_xh[(size_t)M_TOTAL * UNITS];  // x in fp16
__device__ __half g_w1h[UNITS * UNITS];           // W1 in fp16
__device__ float  g_c[NB * UNITS];
__device__ float  g_spart[N_CHUNKS][NB * NT];     // per-chunk score partials
#define CTX_SPLIT 8
__device__ float  g_ctxp[CTX_SPLIT * NB * UNITS];

__device__ __forceinline__ uint32_t sptr(const void* p) {
    return (uint32_t)__cvta_generic_to_shared(p);
}
#define LDMX4(r0, r1, r2, r3, a) \
    asm volatile("ldmatrix.sync.aligned.m8n8.x4.shared.b16 {%0,%1,%2,%3}, [%4];" \
                 : "=r"(r0), "=r"(r1), "=r"(r2), "=r"(r3) : "r"(a))
#define CP16(dst, src) \
    asm volatile("cp.async.cg.shared.global [%0], [%1], 16;" \
                 :: "r"(dst), "l"(src))
#define CP_COMMIT() asm volatile("cp.async.commit_group;" ::: "memory")
#define CP_WAIT1()  asm volatile("cp.async.wait_group 1;" ::: "memory")
#define CP_WAIT0()  asm volatile("cp.async.wait_group 0;" ::: "memory")

__device__ __forceinline__ void mma_f16(float d[4], const uint32_t a[4],
                                        const uint32_t b0, const uint32_t b1) {
    asm volatile(
        "mma.sync.aligned.m16n8k16.row.col.f32.f16.f16.f32 "
        "{%0,%1,%2,%3}, {%4,%5,%6,%7}, {%8,%9}, {%0,%1,%2,%3};"
        : "+f"(d[0]), "+f"(d[1]), "+f"(d[2]), "+f"(d[3])
        : "r"(a[0]), "r"(a[1]), "r"(a[2]), "r"(a[3]), "r"(b0), "r"(b1));
}

// ============ converter: fp32 -> fp16 for x and W1 (one kernel) ============
__device__ __forceinline__ uint2 pack4(float4 v) {
    __half2 lo = __floats2half2_rn(v.x, v.y);
    __half2 hi = __floats2half2_rn(v.z, v.w);
    uint2 r;
    r.x = *(uint32_t*)&lo;
    r.y = *(uint32_t*)&hi;
    return r;
}
#define XBLOCKS ((int)((size_t)M_TOTAL * UNITS / (256 * 8)))   // 32768
#define WBLOCKS (UNITS * UNITS / (256 * 8))                    // 512
__global__ void convert_kernel(const float* __restrict__ x,
                               const float* __restrict__ w1) {
    const int bb = blockIdx.x;
    const float* src;
    __half* dst;
    size_t i;
    if (bb < XBLOCKS) {
        i = ((size_t)bb * 256 + threadIdx.x) * 8;
        src = x;  dst = g_xh;
    } else {
        i = ((size_t)(bb - XBLOCKS) * 256 + threadIdx.x) * 8;
        src = w1; dst = g_w1h;
    }
    const float4 v0 = *(const float4*)(src + i);
    const float4 v1 = *(const float4*)(src + i + 4);
    uint2 a = pack4(v0), b = pack4(v1);
    *(uint4*)(dst + i) = make_uint4(a.x, a.y, b.x, b.y);
}

// ============================ Kernel A: c[b][v] ============================
__global__ void bias_hidden_kernel(const float* __restrict__ hidden,
                                   const float* __restrict__ W2_w,
                                   const float* __restrict__ W1_b,
                                   const float* __restrict__ W2_b) {
    __shared__ float hs[UNITS];
    const int b = blockIdx.x;
    for (int u = threadIdx.x; u < UNITS; u += 256)
        hs[u] = hidden[b * UNITS + u];
    __syncthreads();
    const int warp = threadIdx.x >> 5, lane = threadIdx.x & 31;
    const int v0 = blockIdx.y * 128;
    for (int v = v0 + warp; v < v0 + 128; v += 8) {
        const float* wr = W2_w + (size_t)v * UNITS;
        float s = 0.f;
        #pragma unroll 8
        for (int u = lane; u < UNITS; u += 32) s += hs[u] * wr[u];
        #pragma unroll
        for (int m = 16; m; m >>= 1) s += __shfl_xor_sync(0xffffffffu, s, m);
        if (lane == 0) g_c[b * UNITS + v] = s + W1_b[v] + W2_b[v];
    }
}

// == Kernel B: persistent fp16 mma GEMM (R11 config), direct-L2 bias reads ==
// 148 CTAs x 512 threads (16 warps = 2m x 8n, warp tile 64x32).
// CTA tile 128x256, BK=64, 3-stage cp.async. 2048 items round-robin.
__global__ void __launch_bounds__(512, 1) score_kernel(
    const float* __restrict__ Vw) {
    extern __shared__ char smem[];
    const uint32_t sb = sptr(smem);

    const int tid  = threadIdx.x;
    const int wid  = tid >> 5, lane = tid & 31;
    const int wm   = wid >> 3;          // 0..1  rows wm*64
    const int wn   = wid & 7;           // 0..7  cols wn*32
    const int grp  = lane >> 2;
    const int thr  = lane & 3;

    float* vs = (float*)(smem + S_VS);
    for (int i = tid; i < UNITS; i += 512)
        vs[i] = Vw[i];

    // cp.async mapping (BK=64, 512 thr): A 1024 uint4 -> 2/thr; B 2048 -> 4/thr
    const int lrow = tid >> 3;          // 0..63, +j*64
    const int lseg = tid & 7;           // uint4 within 128B row

    // ldmatrix fragment bases (stage offset added in-loop)
    const uint32_t aF = sb + (uint32_t)((wm * 64 + (lane & 15)) * ROWB
                                        + (lane >> 4) * 16);
    const uint32_t bF = sb + 18432u
        + (uint32_t)((wn * 32 + ((lane >> 4) << 3) + (lane & 7)) * ROWB
                     + ((lane >> 3) & 1) * 16);

    float (*sred)[M_TILE] = (float(*)[M_TILE])(smem + S_RED);

    for (int item = blockIdx.x; item < N_ITEMS; item += GRID_P) {
        const int m_idx = item >> 2;
        const int nc    = item & 3;
        const int m0    = m_idx * M_TILE;
        const int b     = m0 / NT;
        const int n0    = nc * N_CHUNK;
        const __half* xg = g_xh  + (size_t)m0 * UNITS;
        const __half* wg = g_w1h + (size_t)n0 * UNITS;

        float d[4][4][4];
        #pragma unroll
        for (int mf = 0; mf < 4; ++mf)
            #pragma unroll
            for (int nf = 0; nf < 4; ++nf)
                #pragma unroll
                for (int q = 0; q < 4; ++q) d[mf][nf][q] = 0.f;

        // --- async tile fill: stage s <- k-tile kt ---
        #define FILL_TILE(s, kt) do {                                          \
            const uint32_t as = sb + S_A(s);                                   \
            const uint32_t bs = sb + S_B(s);                                   \
            const int kbase = (kt) * BK;                                       \
            _Pragma("unroll")                                                  \
            for (int j = 0; j < 2; ++j) {                                      \
                const int r = lrow + j * 64;                                   \
                CP16(as + r * ROWB + lseg * 16,                                \
                     xg + (size_t)r * UNITS + kbase + lseg * 8);               \
            }                                                                  \
            _Pragma("unroll")                                                  \
            for (int j = 0; j < 4; ++j) {                                      \
                const int r = lrow + j * 64;                                   \
                CP16(bs + r * ROWB + lseg * 16,                                \
                     wg + (size_t)r * UNITS + kbase + lseg * 8);               \
            }                                                                  \
            CP_COMMIT();                                                       \
        } while (0)

        FILL_TILE(0, 0);
        FILL_TILE(1, 1);

        int stage = 0;
        for (int kt = 0; kt < K_TILES; ++kt) {
            if (kt + 1 < K_TILES) { CP_WAIT1(); } else { CP_WAIT0(); }
            __syncthreads();       // tile kt ready

            if (kt + 2 < K_TILES) {
                const int ns = (stage + 2 >= 3) ? stage - 1 : stage + 2;
                FILL_TILE(ns, kt + 2);
            }

            const uint32_t abuf = aF + (uint32_t)(stage * STG);
            const uint32_t bbuf = bF + (uint32_t)(stage * STG);
            #pragma unroll
            for (int ks = 0; ks < 4; ++ks) {
                const uint32_t koff = ks * 32;
                uint32_t af[4][4];
                #pragma unroll
                for (int mf = 0; mf < 4; ++mf)
                    LDMX4(af[mf][0], af[mf][1], af[mf][2], af[mf][3],
                          abuf + mf * 16 * ROWB + koff);
                uint32_t bb[2][4];
                #pragma unroll
                for (int nfp = 0; nfp < 2; ++nfp)
                    LDMX4(bb[nfp][0], bb[nfp][1], bb[nfp][2], bb[nfp][3],
                          bbuf + nfp * 16 * ROWB + koff);
                #pragma unroll
                for (int nfp = 0; nfp < 2; ++nfp) {
                    #pragma unroll
                    for (int mf = 0; mf < 4; ++mf) {
                        mma_f16(d[mf][nfp * 2 + 0], af[mf], bb[nfp][0], bb[nfp][1]);
                        mma_f16(d[mf][nfp * 2 + 1], af[mf], bb[nfp][2], bb[nfp][3]);
                    }
                }
            }
            stage = (stage == 2) ? 0 : stage + 1;
        }
        #undef FILL_TILE

        // Epilogue: tanh + V-weighted reduce. Bias c read direct from L2
        // (g_c is 128KB, L2-resident; 8 values per thread, reused across mf).
        const float* cb = g_c + b * UNITS;
        float cv[4][2], vv[4][2];
        #pragma unroll
        for (int nf = 0; nf < 4; ++nf) {
            const int n = n0 + wn * 32 + nf * 8 + 2 * thr;
            cv[nf][0] = __ldg(cb + n);     cv[nf][1] = __ldg(cb + n + 1);
            vv[nf][0] = vs[n];             vv[nf][1] = vs[n + 1];
        }
        float sacc[4][2];
        #pragma unroll
        for (int mf = 0; mf < 4; ++mf) {
            sacc[mf][0] = 0.f; sacc[mf][1] = 0.f;
            #pragma unroll
            for (int nf = 0; nf < 4; ++nf) {
                sacc[mf][0] += tanhf(d[mf][nf][0] + cv[nf][0]) * vv[nf][0];
                sacc[mf][0] += tanhf(d[mf][nf][1] + cv[nf][1]) * vv[nf][1];
                sacc[mf][1] += tanhf(d[mf][nf][2] + cv[nf][0]) * vv[nf][0];
                sacc[mf][1] += tanhf(d[mf][nf][3] + cv[nf][1]) * vv[nf][1];
            }
        }

        __syncthreads();    // all ldmatrix done; sred buffer free
        #pragma unroll
        for (int mf = 0; mf < 4; ++mf) {
            #pragma unroll
            for (int h = 0; h < 2; ++h) {
                float v = sacc[mf][h];
                v += __shfl_xor_sync(0xffffffffu, v, 1);
                v += __shfl_xor_sync(0xffffffffu, v, 2);
                if (thr == 0)
                    sred[wn][wm * 64 + mf * 16 + h * 8 + grp] = v;
            }
        }
        __syncthreads();
        if (tid < M_TILE) {
            float s = 0.f;
            #pragma unroll
            for (int w = 0; w < 8; ++w) s += sred[w][tid];
            g_spart[nc][m0 + tid] = s;
        }
        __syncthreads();    // sred reads done before next item reuses smem
    }
}

// ============ Kernel C: softmax per batch (sums 4 chunk partials) ==========
__global__ void softmax_kernel(float* __restrict__ out_w) {
    __shared__ float s[NT];
    __shared__ float red[32];
    const int b = blockIdx.x;
    const int tid = threadIdx.x;
    const int lane = tid & 31, warp = tid >> 5;

    float lmax = -INFINITY;
    for (int t = tid; t < NT; t += 256) {
        const int i = b * NT + t;
        const float v = (g_spart[0][i] + g_spart[1][i])
                      + (g_spart[2][i] + g_spart[3][i]);
        s[t] = v;
        lmax = fmaxf(lmax, v);
    }
    #pragma unroll
    for (int m = 16; m; m >>= 1)
        lmax = fmaxf(lmax, __shfl_xor_sync(0xffffffffu, lmax, m));
    if (lane == 0) red[warp] = lmax;
    __syncthreads();
    float bmax = red[0];
    #pragma unroll
    for (int w = 1; w < 8; w++) bmax = fmaxf(bmax, red[w]);

    float lsum = 0.f;
    for (int t = tid; t < NT; t += 256) {
        const float e = __expf(s[t] - bmax);
        s[t] = e;
        lsum += e;
    }
    #pragma unroll
    for (int m = 16; m; m >>= 1)
        lsum += __shfl_xor_sync(0xffffffffu, lsum, m);
    __syncthreads();
    if (lane == 0) red[warp] = lsum;
    __syncthreads();
    float bsum = 0.f;
    #pragma unroll
    for (int w = 0; w < 8; w++) bsum += red[w];
    const float inv = 1.f / bsum;
    for (int t = tid; t < NT; t += 256)
        out_w[b * NT + t] = s[t] * inv;
}

// ====== Kernel D: context partials (8-way t-split, fp16 x) =================
__global__ void __launch_bounds__(256) context_part_kernel(
    const float* __restrict__ w) {
    __shared__ float ws[NT / CTX_SPLIT];    // 256
    const int b  = blockIdx.x;
    const int uc = blockIdx.y;
    const int tc = blockIdx.z;
    const int t0 = tc * (NT / CTX_SPLIT);
    ws[threadIdx.x] = w[b * NT + t0 + threadIdx.x];
    __syncthreads();
    const int u = uc * 256 + threadIdx.x;
    const __half* xp = g_xh + (size_t)b * NT * UNITS + (size_t)t0 * UNITS + u;
    float a0 = 0.f, a1 = 0.f, a2 = 0.f, a3 = 0.f;
    for (int t = 0; t < NT / CTX_SPLIT; t += 4) {
        a0 += ws[t + 0] * __half2float(xp[(size_t)(t + 0) * UNITS]);
        a1 += ws[t + 1] * __half2float(xp[(size_t)(t + 1) * UNITS]);
        a2 += ws[t + 2] * __half2float(xp[(size_t)(t + 2) * UNITS]);
        a3 += ws[t + 3] * __half2float(xp[(size_t)(t + 3) * UNITS]);
    }
    g_ctxp[(size_t)tc * NB * UNITS + b * UNITS + u] = (a0 + a1) + (a2 + a3);
}

__global__ void context_reduce_kernel(float* __restrict__ out_ctx) {
    const int i = blockIdx.x * 256 + threadIdx.x;
    float s = 0.f;
    #pragma unroll
    for (int p = 0; p < CTX_SPLIT; ++p)
        s += g_ctxp[(size_t)p * NB * UNITS + i];
    out_ctx[i] = s;
}

// ---------------------------------------------------------------------------
extern "C" void kernel_launch(void* const* d_in, const int* in_sizes, int n_in,
                              void* d_out, int out_size) {
    const float* x      = (const float*)d_in[0];
    const float* hidden = (const float*)d_in[1];
    const float* W1_w   = (const float*)d_in[2];
    const float* W1_b   = (const float*)d_in[3];
    const float* W2_w   = (const float*)d_in[4];
    const float* W2_b   = (const float*)d_in[5];
    const float* V_w    = (const float*)d_in[6];
    // d_in[7] = V_b: softmax-invariant, unused.

    float* out     = (float*)d_out;
    float* out_ctx = out;                   // 32*1024
    float* out_w   = out + NB * UNITS;      // 32*2048

    cudaFuncSetAttribute(score_kernel,
                         cudaFuncAttributeMaxDynamicSharedMemorySize, S_TOTAL);

    convert_kernel<<<XBLOCKS + WBLOCKS, 256>>>(x, W1_w);
    bias_hidden_kernel<<<dim3(NB, 8), 256>>>(hidden, W2_w, W1_b, W2_b);
    score_kernel<<<GRID_P, 512, S_TOTAL>>>(V_w);
    softmax_kernel<<<NB, 256>>>(out_w);
    context_part_kernel<<<dim3(NB, 4, CTX_SPLIT), 256>>>(out_w);
    context_reduce_kernel<<<NB * UNITS / 256, 256>>>(out_ctx);
}

// round 14
// speedup vs baseline: 1.1650x; 1.0555x over previous
#include <cuda_runtime.h>
#include <cuda_fp16.h>
#include <math.h>
#include <stdint.h>

#define UNITS 1024
#define NB    32
#define NT    2048
#define M_TOTAL (NB * NT)

#define M_TILE 128
#define N_CHUNK 256
#define BK 64
#define N_CHUNKS (UNITS / N_CHUNK)   // 4
#define K_TILES  (UNITS / BK)        // 16
#define N_ITEMS  ((M_TOTAL / M_TILE) * N_CHUNKS)   // 2048
#define GRID_P   148
#define PADH 8
#define ROWH (BK + PADH)             // 72 halves
#define ROWB (ROWH * 2)              // 144 bytes

// smem: 3 stages of (A:128x144B=18432, B:256x144B=36864)
#define STG    55296
#define S_A(s) ((s) * STG)
#define S_B(s) ((s) * STG + 18432)
#define S_CS   165888
#define S_VS   169984
#define S_RED  174080                // float[8][128] = 4KB
#define S_TOTAL 178176

// ---- scratch (allocation-free rule: __device__ globals) ----
__device__ __half g_xh[(size_t)M_TOTAL * UNITS];  // x in fp16
__device__ __half g_w1h[UNITS * UNITS];           // W1 in fp16
__device__ float  g_c[NB * UNITS];
__device__ float  g_spart[N_CHUNKS][NB * NT];     // per-chunk score partials
#define CTX_SPLIT 8
__device__ float  g_ctxp[CTX_SPLIT * NB * UNITS];

__device__ __forceinline__ uint32_t sptr(const void* p) {
    return (uint32_t)__cvta_generic_to_shared(p);
}
__device__ __forceinline__ float tanh_fast(float x) {
    float y;
    asm("tanh.approx.f32 %0, %1;" : "=f"(y) : "f"(x));
    return y;
}
#define LDMX4(r0, r1, r2, r3, a) \
    asm volatile("ldmatrix.sync.aligned.m8n8.x4.shared.b16 {%0,%1,%2,%3}, [%4];" \
                 : "=r"(r0), "=r"(r1), "=r"(r2), "=r"(r3) : "r"(a))
#define CP16(dst, src) \
    asm volatile("cp.async.cg.shared.global [%0], [%1], 16;" \
                 :: "r"(dst), "l"(src))
#define CP_COMMIT() asm volatile("cp.async.commit_group;" ::: "memory")
#define CP_WAIT1()  asm volatile("cp.async.wait_group 1;" ::: "memory")
#define CP_WAIT0()  asm volatile("cp.async.wait_group 0;" ::: "memory")

__device__ __forceinline__ void mma_f16(float d[4], const uint32_t a[4],
                                        const uint32_t b0, const uint32_t b1) {
    asm volatile(
        "mma.sync.aligned.m16n8k16.row.col.f32.f16.f16.f32 "
        "{%0,%1,%2,%3}, {%4,%5,%6,%7}, {%8,%9}, {%0,%1,%2,%3};"
        : "+f"(d[0]), "+f"(d[1]), "+f"(d[2]), "+f"(d[3])
        : "r"(a[0]), "r"(a[1]), "r"(a[2]), "r"(a[3]), "r"(b0), "r"(b1));
}

// ===== prep kernel: convert x, convert W1, and compute bias c[b][v] ========
__device__ __forceinline__ uint2 pack4(float4 v) {
    __half2 lo = __floats2half2_rn(v.x, v.y);
    __half2 hi = __floats2half2_rn(v.z, v.w);
    uint2 r;
    r.x = *(uint32_t*)&lo;
    r.y = *(uint32_t*)&hi;
    return r;
}
#define XBLOCKS ((int)((size_t)M_TOTAL * UNITS / (256 * 8)))   // 32768
#define WBLOCKS (UNITS * UNITS / (256 * 8))                    // 512
#define BBLOCKS (NB * 8)                                       // 256
__global__ void prep_kernel(const float* __restrict__ x,
                            const float* __restrict__ w1,
                            const float* __restrict__ hidden,
                            const float* __restrict__ W2_w,
                            const float* __restrict__ W1_b,
                            const float* __restrict__ W2_b) {
    __shared__ float hs[UNITS];
    const int bb = blockIdx.x;
    if (bb < XBLOCKS + WBLOCKS) {
        const float* src;
        __half* dst;
        size_t i;
        if (bb < XBLOCKS) {
            i = ((size_t)bb * 256 + threadIdx.x) * 8;
            src = x;  dst = g_xh;
        } else {
            i = ((size_t)(bb - XBLOCKS) * 256 + threadIdx.x) * 8;
            src = w1; dst = g_w1h;
        }
        const float4 v0 = *(const float4*)(src + i);
        const float4 v1 = *(const float4*)(src + i + 4);
        uint2 a = pack4(v0), b = pack4(v1);
        *(uint4*)(dst + i) = make_uint4(a.x, a.y, b.x, b.y);
    } else {
        const int idx = bb - XBLOCKS - WBLOCKS;   // 0..255
        const int b   = idx >> 3;
        const int v0  = (idx & 7) * 128;
        for (int u = threadIdx.x; u < UNITS; u += 256)
            hs[u] = hidden[b * UNITS + u];
        __syncthreads();
        const int warp = threadIdx.x >> 5, lane = threadIdx.x & 31;
        for (int v = v0 + warp; v < v0 + 128; v += 8) {
            const float* wr = W2_w + (size_t)v * UNITS;
            float s = 0.f;
            #pragma unroll 8
            for (int u = lane; u < UNITS; u += 32) s += hs[u] * wr[u];
            #pragma unroll
            for (int m = 16; m; m >>= 1)
                s += __shfl_xor_sync(0xffffffffu, s, m);
            if (lane == 0) g_c[b * UNITS + v] = s + W1_b[v] + W2_b[v];
        }
    }
}

// == Kernel B: persistent fp16 mma GEMM (R11 config) + fast-tanh epilogue ===
// 148 CTAs x 512 threads (16 warps = 2m x 8n, warp tile 64x32).
// CTA tile 128x256, BK=64, 3-stage cp.async. 2048 items round-robin.
__global__ void __launch_bounds__(512, 1) score_kernel(
    const float* __restrict__ Vw) {
    extern __shared__ char smem[];
    const uint32_t sb = sptr(smem);

    const int tid  = threadIdx.x;
    const int wid  = tid >> 5, lane = tid & 31;
    const int wm   = wid >> 3;          // 0..1  rows wm*64
    const int wn   = wid & 7;           // 0..7  cols wn*32
    const int grp  = lane >> 2;
    const int thr  = lane & 3;

    float* cs = (float*)(smem + S_CS);
    float* vs = (float*)(smem + S_VS);
    for (int i = tid; i < UNITS; i += 512)
        vs[i] = Vw[i];

    // cp.async mapping (BK=64, 512 thr): A 1024 uint4 -> 2/thr; B 2048 -> 4/thr
    const int lrow = tid >> 3;          // 0..63, +j*64
    const int lseg = tid & 7;           // uint4 within 128B row

    // ldmatrix fragment bases (stage offset added in-loop)
    const uint32_t aF = sb + (uint32_t)((wm * 64 + (lane & 15)) * ROWB
                                        + (lane >> 4) * 16);
    const uint32_t bF = sb + 18432u
        + (uint32_t)((wn * 32 + ((lane >> 4) << 3) + (lane & 7)) * ROWB
                     + ((lane >> 3) & 1) * 16);

    float (*sred)[M_TILE] = (float(*)[M_TILE])(smem + S_RED);

    for (int item = blockIdx.x; item < N_ITEMS; item += GRID_P) {
        const int m_idx = item >> 2;
        const int nc    = item & 3;
        const int m0    = m_idx * M_TILE;
        const int b     = m0 / NT;
        const int n0    = nc * N_CHUNK;
        const __half* xg = g_xh  + (size_t)m0 * UNITS;
        const __half* wg = g_w1h + (size_t)n0 * UNITS;

        float d[4][4][4];
        #pragma unroll
        for (int mf = 0; mf < 4; ++mf)
            #pragma unroll
            for (int nf = 0; nf < 4; ++nf)
                #pragma unroll
                for (int q = 0; q < 4; ++q) d[mf][nf][q] = 0.f;

        // --- async tile fill: stage s <- k-tile kt ---
        #define FILL_TILE(s, kt) do {                                          \
            const uint32_t as = sb + S_A(s);                                   \
            const uint32_t bs = sb + S_B(s);                                   \
            const int kbase = (kt) * BK;                                       \
            _Pragma("unroll")                                                  \
            for (int j = 0; j < 2; ++j) {                                      \
                const int r = lrow + j * 64;                                   \
                CP16(as + r * ROWB + lseg * 16,                                \
                     xg + (size_t)r * UNITS + kbase + lseg * 8);               \
            }                                                                  \
            _Pragma("unroll")                                                  \
            for (int j = 0; j < 4; ++j) {                                      \
                const int r = lrow + j * 64;                                   \
                CP16(bs + r * ROWB + lseg * 16,                                \
                     wg + (size_t)r * UNITS + kbase + lseg * 8);               \
            }                                                                  \
            CP_COMMIT();                                                       \
        } while (0)

        FILL_TILE(0, 0);
        FILL_TILE(1, 1);

        // per-item bias vector (safe: prev item's cs reads ended before its
        // last __syncthreads)
        for (int i = tid; i < UNITS; i += 512)
            cs[i] = g_c[b * UNITS + i];

        int stage = 0;
        for (int kt = 0; kt < K_TILES; ++kt) {
            if (kt + 1 < K_TILES) { CP_WAIT1(); } else { CP_WAIT0(); }
            __syncthreads();       // tile kt ready (and cs visible)

            if (kt + 2 < K_TILES) {
                const int ns = (stage + 2 >= 3) ? stage - 1 : stage + 2;
                FILL_TILE(ns, kt + 2);
            }

            const uint32_t abuf = aF + (uint32_t)(stage * STG);
            const uint32_t bbuf = bF + (uint32_t)(stage * STG);
            #pragma unroll
            for (int ks = 0; ks < 4; ++ks) {
                const uint32_t koff = ks * 32;
                uint32_t af[4][4];
                #pragma unroll
                for (int mf = 0; mf < 4; ++mf)
                    LDMX4(af[mf][0], af[mf][1], af[mf][2], af[mf][3],
                          abuf + mf * 16 * ROWB + koff);
                uint32_t bb[2][4];
                #pragma unroll
                for (int nfp = 0; nfp < 2; ++nfp)
                    LDMX4(bb[nfp][0], bb[nfp][1], bb[nfp][2], bb[nfp][3],
                          bbuf + nfp * 16 * ROWB + koff);
                #pragma unroll
                for (int nfp = 0; nfp < 2; ++nfp) {
                    #pragma unroll
                    for (int mf = 0; mf < 4; ++mf) {
                        mma_f16(d[mf][nfp * 2 + 0], af[mf], bb[nfp][0], bb[nfp][1]);
                        mma_f16(d[mf][nfp * 2 + 1], af[mf], bb[nfp][2], bb[nfp][3]);
                    }
                }
            }
            stage = (stage == 2) ? 0 : stage + 1;
        }
        #undef FILL_TILE

        // Epilogue: HW-approx tanh + V-weighted reduce (this n-chunk)
        float sacc[4][2];
        #pragma unroll
        for (int mf = 0; mf < 4; ++mf) {
            sacc[mf][0] = 0.f; sacc[mf][1] = 0.f;
            #pragma unroll
            for (int nf = 0; nf < 4; ++nf) {
                const int n = n0 + wn * 32 + nf * 8 + 2 * thr;
                sacc[mf][0] += tanh_fast(d[mf][nf][0] + cs[n])     * vs[n];
                sacc[mf][0] += tanh_fast(d[mf][nf][1] + cs[n + 1]) * vs[n + 1];
                sacc[mf][1] += tanh_fast(d[mf][nf][2] + cs[n])     * vs[n];
                sacc[mf][1] += tanh_fast(d[mf][nf][3] + cs[n + 1]) * vs[n + 1];
            }
        }

        __syncthreads();    // all ldmatrix done; sred buffer free
        #pragma unroll
        for (int mf = 0; mf < 4; ++mf) {
            #pragma unroll
            for (int h = 0; h < 2; ++h) {
                float v = sacc[mf][h];
                v += __shfl_xor_sync(0xffffffffu, v, 1);
                v += __shfl_xor_sync(0xffffffffu, v, 2);
                if (thr == 0)
                    sred[wn][wm * 64 + mf * 16 + h * 8 + grp] = v;
            }
        }
        __syncthreads();
        if (tid < M_TILE) {
            float s = 0.f;
            #pragma unroll
            for (int w = 0; w < 8; ++w) s += sred[w][tid];
            g_spart[nc][m0 + tid] = s;
        }
        __syncthreads();    // sred reads done before next item reuses smem
    }
}

// ============ Kernel C: softmax per batch (sums 4 chunk partials) ==========
__global__ void softmax_kernel(float* __restrict__ out_w) {
    __shared__ float s[NT];
    __shared__ float red[32];
    const int b = blockIdx.x;
    const int tid = threadIdx.x;
    const int lane = tid & 31, warp = tid >> 5;

    float lmax = -INFINITY;
    for (int t = tid; t < NT; t += 256) {
        const int i = b * NT + t;
        const float v = (g_spart[0][i] + g_spart[1][i])
                      + (g_spart[2][i] + g_spart[3][i]);
        s[t] = v;
        lmax = fmaxf(lmax, v);
    }
    #pragma unroll
    for (int m = 16; m; m >>= 1)
        lmax = fmaxf(lmax, __shfl_xor_sync(0xffffffffu, lmax, m));
    if (lane == 0) red[warp] = lmax;
    __syncthreads();
    float bmax = red[0];
    #pragma unroll
    for (int w = 1; w < 8; w++) bmax = fmaxf(bmax, red[w]);

    float lsum = 0.f;
    for (int t = tid; t < NT; t += 256) {
        const float e = __expf(s[t] - bmax);
        s[t] = e;
        lsum += e;
    }
    #pragma unroll
    for (int m = 16; m; m >>= 1)
        lsum += __shfl_xor_sync(0xffffffffu, lsum, m);
    __syncthreads();
    if (lane == 0) red[warp] = lsum;
    __syncthreads();
    float bsum = 0.f;
    #pragma unroll
    for (int w = 0; w < 8; w++) bsum += red[w];
    const float inv = 1.f / bsum;
    for (int t = tid; t < NT; t += 256)
        out_w[b * NT + t] = s[t] * inv;
}

// ====== Kernel D: context partials (8-way t-split, fp16 x) =================
__global__ void __launch_bounds__(256) context_part_kernel(
    const float* __restrict__ w) {
    __shared__ float ws[NT / CTX_SPLIT];    // 256
    const int b  = blockIdx.x;
    const int uc = blockIdx.y;
    const int tc = blockIdx.z;
    const int t0 = tc * (NT / CTX_SPLIT);
    ws[threadIdx.x] = w[b * NT + t0 + threadIdx.x];
    __syncthreads();
    const int u = uc * 256 + threadIdx.x;
    const __half* xp = g_xh + (size_t)b * NT * UNITS + (size_t)t0 * UNITS + u;
    float a0 = 0.f, a1 = 0.f, a2 = 0.f, a3 = 0.f;
    for (int t = 0; t < NT / CTX_SPLIT; t += 4) {
        a0 += ws[t + 0] * __half2float(xp[(size_t)(t + 0) * UNITS]);
        a1 += ws[t + 1] * __half2float(xp[(size_t)(t + 1) * UNITS]);
        a2 += ws[t + 2] * __half2float(xp[(size_t)(t + 2) * UNITS]);
        a3 += ws[t + 3] * __half2float(xp[(size_t)(t + 3) * UNITS]);
    }
    g_ctxp[(size_t)tc * NB * UNITS + b * UNITS + u] = (a0 + a1) + (a2 + a3);
}

__global__ void context_reduce_kernel(float* __restrict__ out_ctx) {
    const int i = blockIdx.x * 256 + threadIdx.x;
    float s = 0.f;
    #pragma unroll
    for (int p = 0; p < CTX_SPLIT; ++p)
        s += g_ctxp[(size_t)p * NB * UNITS + i];
    out_ctx[i] = s;
}

// ---------------------------------------------------------------------------
extern "C" void kernel_launch(void* const* d_in, const int* in_sizes, int n_in,
                              void* d_out, int out_size) {
    const float* x      = (const float*)d_in[0];
    const float* hidden = (const float*)d_in[1];
    const float* W1_w   = (const float*)d_in[2];
    const float* W1_b   = (const float*)d_in[3];
    const float* W2_w   = (const float*)d_in[4];
    const float* W2_b   = (const float*)d_in[5];
    const float* V_w    = (const float*)d_in[6];
    // d_in[7] = V_b: softmax-invariant, unused.

    float* out     = (float*)d_out;
    float* out_ctx = out;                   // 32*1024
    float* out_w   = out + NB * UNITS;      // 32*2048

    cudaFuncSetAttribute(score_kernel,
                         cudaFuncAttributeMaxDynamicSharedMemorySize, S_TOTAL);

    prep_kernel<<<XBLOCKS + WBLOCKS + BBLOCKS, 256>>>(x, W1_w, hidden,
                                                      W2_w, W1_b, W2_b);
    score_kernel<<<GRID_P, 512, S_TOTAL>>>(V_w);
    softmax_kernel<<<NB, 256>>>(out_w);
    context_part_kernel<<<dim3(NB, 4, CTX_SPLIT), 256>>>(out_w);
    context_reduce_kernel<<<NB * UNITS / 256, 256>>>(out_ctx);
}

// round 15
// speedup vs baseline: 1.1919x; 1.0231x over previous
#include <cuda_runtime.h>
#include <cuda_fp16.h>
#include <math.h>
#include <stdint.h>

#define UNITS 1024
#define NB    32
#define NT    2048
#define M_TOTAL (NB * NT)

#define M_TILE 128
#define N_CHUNK 256
#define BK 64
#define N_CHUNKS (UNITS / N_CHUNK)   // 4
#define K_TILES  (UNITS / BK)        // 16
#define N_ITEMS  ((M_TOTAL / M_TILE) * N_CHUNKS)   // 2048
#define GRID_P   148
#define PADH 8
#define ROWH (BK + PADH)             // 72 halves
#define ROWB (ROWH * 2)              // 144 bytes

// smem: 3 stages of (A:128x144B=18432, B:256x144B=36864)
#define STG    55296
#define S_A(s) ((s) * STG)
#define S_B(s) ((s) * STG + 18432)
#define S_CS   165888
#define S_VS   169984
#define S_RED  174080                // float[8][128] = 4KB
#define S_TOTAL 178176

// ---- scratch (allocation-free rule: __device__ globals) ----
__device__ __half g_xh[(size_t)M_TOTAL * UNITS];  // x in fp16
__device__ __half g_w1h[UNITS * UNITS];           // W1 in fp16
__device__ float  g_c[NB * UNITS];
__device__ float  g_spart[N_CHUNKS][NB * NT];     // per-chunk score partials
#define CTX_SPLIT 16
#define T_SLICE   (NT / CTX_SPLIT)   // 128
__device__ float  g_ctxp[CTX_SPLIT * NB * UNITS]; // 2MB

__device__ __forceinline__ uint32_t sptr(const void* p) {
    return (uint32_t)__cvta_generic_to_shared(p);
}
__device__ __forceinline__ float tanh_fast(float x) {
    float y;
    asm("tanh.approx.f32 %0, %1;" : "=f"(y) : "f"(x));
    return y;
}
#define LDMX4(r0, r1, r2, r3, a) \
    asm volatile("ldmatrix.sync.aligned.m8n8.x4.shared.b16 {%0,%1,%2,%3}, [%4];" \
                 : "=r"(r0), "=r"(r1), "=r"(r2), "=r"(r3) : "r"(a))
#define CP16(dst, src) \
    asm volatile("cp.async.cg.shared.global [%0], [%1], 16;" \
                 :: "r"(dst), "l"(src))
#define CP_COMMIT() asm volatile("cp.async.commit_group;" ::: "memory")
#define CP_WAIT1()  asm volatile("cp.async.wait_group 1;" ::: "memory")
#define CP_WAIT0()  asm volatile("cp.async.wait_group 0;" ::: "memory")

__device__ __forceinline__ void mma_f16(float d[4], const uint32_t a[4],
                                        const uint32_t b0, const uint32_t b1) {
    asm volatile(
        "mma.sync.aligned.m16n8k16.row.col.f32.f16.f16.f32 "
        "{%0,%1,%2,%3}, {%4,%5,%6,%7}, {%8,%9}, {%0,%1,%2,%3};"
        : "+f"(d[0]), "+f"(d[1]), "+f"(d[2]), "+f"(d[3])
        : "r"(a[0]), "r"(a[1]), "r"(a[2]), "r"(a[3]), "r"(b0), "r"(b1));
}

// ===== prep kernel: convert x, convert W1, and compute bias c[b][v] ========
__device__ __forceinline__ uint2 pack4(float4 v) {
    __half2 lo = __floats2half2_rn(v.x, v.y);
    __half2 hi = __floats2half2_rn(v.z, v.w);
    uint2 r;
    r.x = *(uint32_t*)&lo;
    r.y = *(uint32_t*)&hi;
    return r;
}
#define XBLOCKS ((int)((size_t)M_TOTAL * UNITS / (256 * 8)))   // 32768
#define WBLOCKS (UNITS * UNITS / (256 * 8))                    // 512
#define BBLOCKS (NB * 8)                                       // 256
__global__ void prep_kernel(const float* __restrict__ x,
                            const float* __restrict__ w1,
                            const float* __restrict__ hidden,
                            const float* __restrict__ W2_w,
                            const float* __restrict__ W1_b,
                            const float* __restrict__ W2_b) {
    __shared__ float hs[UNITS];
    const int bb = blockIdx.x;
    if (bb < XBLOCKS + WBLOCKS) {
        const float* src;
        __half* dst;
        size_t i;
        if (bb < XBLOCKS) {
            i = ((size_t)bb * 256 + threadIdx.x) * 8;
            src = x;  dst = g_xh;
        } else {
            i = ((size_t)(bb - XBLOCKS) * 256 + threadIdx.x) * 8;
            src = w1; dst = g_w1h;
        }
        const float4 v0 = *(const float4*)(src + i);
        const float4 v1 = *(const float4*)(src + i + 4);
        uint2 a = pack4(v0), b = pack4(v1);
        *(uint4*)(dst + i) = make_uint4(a.x, a.y, b.x, b.y);
    } else {
        const int idx = bb - XBLOCKS - WBLOCKS;   // 0..255
        const int b   = idx >> 3;
        const int v0  = (idx & 7) * 128;
        for (int u = threadIdx.x; u < UNITS; u += 256)
            hs[u] = hidden[b * UNITS + u];
        __syncthreads();
        const int warp = threadIdx.x >> 5, lane = threadIdx.x & 31;
        for (int v = v0 + warp; v < v0 + 128; v += 8) {
            const float* wr = W2_w + (size_t)v * UNITS;
            float s = 0.f;
            #pragma unroll 8
            for (int u = lane; u < UNITS; u += 32) s += hs[u] * wr[u];
            #pragma unroll
            for (int m = 16; m; m >>= 1)
                s += __shfl_xor_sync(0xffffffffu, s, m);
            if (lane == 0) g_c[b * UNITS + v] = s + W1_b[v] + W2_b[v];
        }
    }
}

// == Kernel B: persistent fp16 mma GEMM (R11 config) + fast-tanh epilogue ===
// 148 CTAs x 512 threads (16 warps = 2m x 8n, warp tile 64x32).
// CTA tile 128x256, BK=64, 3-stage cp.async. 2048 items round-robin.
__global__ void __launch_bounds__(512, 1) score_kernel(
    const float* __restrict__ Vw) {
    extern __shared__ char smem[];
    const uint32_t sb = sptr(smem);

    const int tid  = threadIdx.x;
    const int wid  = tid >> 5, lane = tid & 31;
    const int wm   = wid >> 3;          // 0..1  rows wm*64
    const int wn   = wid & 7;           // 0..7  cols wn*32
    const int grp  = lane >> 2;
    const int thr  = lane & 3;

    float* cs = (float*)(smem + S_CS);
    float* vs = (float*)(smem + S_VS);
    for (int i = tid; i < UNITS; i += 512)
        vs[i] = Vw[i];

    // cp.async mapping (BK=64, 512 thr): A 1024 uint4 -> 2/thr; B 2048 -> 4/thr
    const int lrow = tid >> 3;          // 0..63, +j*64
    const int lseg = tid & 7;           // uint4 within 128B row

    // ldmatrix fragment bases (stage offset added in-loop)
    const uint32_t aF = sb + (uint32_t)((wm * 64 + (lane & 15)) * ROWB
                                        + (lane >> 4) * 16);
    const uint32_t bF = sb + 18432u
        + (uint32_t)((wn * 32 + ((lane >> 4) << 3) + (lane & 7)) * ROWB
                     + ((lane >> 3) & 1) * 16);

    float (*sred)[M_TILE] = (float(*)[M_TILE])(smem + S_RED);

    for (int item = blockIdx.x; item < N_ITEMS; item += GRID_P) {
        const int m_idx = item >> 2;
        const int nc    = item & 3;
        const int m0    = m_idx * M_TILE;
        const int b     = m0 / NT;
        const int n0    = nc * N_CHUNK;
        const __half* xg = g_xh  + (size_t)m0 * UNITS;
        const __half* wg = g_w1h + (size_t)n0 * UNITS;

        float d[4][4][4];
        #pragma unroll
        for (int mf = 0; mf < 4; ++mf)
            #pragma unroll
            for (int nf = 0; nf < 4; ++nf)
                #pragma unroll
                for (int q = 0; q < 4; ++q) d[mf][nf][q] = 0.f;

        // --- async tile fill: stage s <- k-tile kt ---
        #define FILL_TILE(s, kt) do {                                          \
            const uint32_t as = sb + S_A(s);                                   \
            const uint32_t bs = sb + S_B(s);                                   \
            const int kbase = (kt) * BK;                                       \
            _Pragma("unroll")                                                  \
            for (int j = 0; j < 2; ++j) {                                      \
                const int r = lrow + j * 64;                                   \
                CP16(as + r * ROWB + lseg * 16,                                \
                     xg + (size_t)r * UNITS + kbase + lseg * 8);               \
            }                                                                  \
            _Pragma("unroll")                                                  \
            for (int j = 0; j < 4; ++j) {                                      \
                const int r = lrow + j * 64;                                   \
                CP16(bs + r * ROWB + lseg * 16,                                \
                     wg + (size_t)r * UNITS + kbase + lseg * 8);               \
            }                                                                  \
            CP_COMMIT();                                                       \
        } while (0)

        FILL_TILE(0, 0);
        FILL_TILE(1, 1);

        // per-item bias vector (safe: prev item's cs reads ended before its
        // last __syncthreads)
        for (int i = tid; i < UNITS; i += 512)
            cs[i] = g_c[b * UNITS + i];

        int stage = 0;
        for (int kt = 0; kt < K_TILES; ++kt) {
            if (kt + 1 < K_TILES) { CP_WAIT1(); } else { CP_WAIT0(); }
            __syncthreads();       // tile kt ready (and cs visible)

            if (kt + 2 < K_TILES) {
                const int ns = (stage + 2 >= 3) ? stage - 1 : stage + 2;
                FILL_TILE(ns, kt + 2);
            }

            const uint32_t abuf = aF + (uint32_t)(stage * STG);
            const uint32_t bbuf = bF + (uint32_t)(stage * STG);
            #pragma unroll
            for (int ks = 0; ks < 4; ++ks) {
                const uint32_t koff = ks * 32;
                uint32_t af[4][4];
                #pragma unroll
                for (int mf = 0; mf < 4; ++mf)
                    LDMX4(af[mf][0], af[mf][1], af[mf][2], af[mf][3],
                          abuf + mf * 16 * ROWB + koff);
                uint32_t bb[2][4];
                #pragma unroll
                for (int nfp = 0; nfp < 2; ++nfp)
                    LDMX4(bb[nfp][0], bb[nfp][1], bb[nfp][2], bb[nfp][3],
                          bbuf + nfp * 16 * ROWB + koff);
                #pragma unroll
                for (int nfp = 0; nfp < 2; ++nfp) {
                    #pragma unroll
                    for (int mf = 0; mf < 4; ++mf) {
                        mma_f16(d[mf][nfp * 2 + 0], af[mf], bb[nfp][0], bb[nfp][1]);
                        mma_f16(d[mf][nfp * 2 + 1], af[mf], bb[nfp][2], bb[nfp][3]);
                    }
                }
            }
            stage = (stage == 2) ? 0 : stage + 1;
        }
        #undef FILL_TILE

        // Epilogue: HW-approx tanh + V-weighted reduce (this n-chunk)
        float sacc[4][2];
        #pragma unroll
        for (int mf = 0; mf < 4; ++mf) {
            sacc[mf][0] = 0.f; sacc[mf][1] = 0.f;
            #pragma unroll
            for (int nf = 0; nf < 4; ++nf) {
                const int n = n0 + wn * 32 + nf * 8 + 2 * thr;
                sacc[mf][0] += tanh_fast(d[mf][nf][0] + cs[n])     * vs[n];
                sacc[mf][0] += tanh_fast(d[mf][nf][1] + cs[n + 1]) * vs[n + 1];
                sacc[mf][1] += tanh_fast(d[mf][nf][2] + cs[n])     * vs[n];
                sacc[mf][1] += tanh_fast(d[mf][nf][3] + cs[n + 1]) * vs[n + 1];
            }
        }

        __syncthreads();    // all ldmatrix done; sred buffer free
        #pragma unroll
        for (int mf = 0; mf < 4; ++mf) {
            #pragma unroll
            for (int h = 0; h < 2; ++h) {
                float v = sacc[mf][h];
                v += __shfl_xor_sync(0xffffffffu, v, 1);
                v += __shfl_xor_sync(0xffffffffu, v, 2);
                if (thr == 0)
                    sred[wn][wm * 64 + mf * 16 + h * 8 + grp] = v;
            }
        }
        __syncthreads();
        if (tid < M_TILE) {
            float s = 0.f;
            #pragma unroll
            for (int w = 0; w < 8; ++w) s += sred[w][tid];
            g_spart[nc][m0 + tid] = s;
        }
        __syncthreads();    // sred reads done before next item reuses smem
    }
}

// ============ Kernel C: softmax per batch (sums 4 chunk partials) ==========
__global__ void softmax_kernel(float* __restrict__ out_w) {
    __shared__ float s[NT];
    __shared__ float red[32];
    const int b = blockIdx.x;
    const int tid = threadIdx.x;
    const int lane = tid & 31, warp = tid >> 5;

    float lmax = -INFINITY;
    for (int t = tid; t < NT; t += 256) {
        const int i = b * NT + t;
        const float v = (g_spart[0][i] + g_spart[1][i])
                      + (g_spart[2][i] + g_spart[3][i]);
        s[t] = v;
        lmax = fmaxf(lmax, v);
    }
    #pragma unroll
    for (int m = 16; m; m >>= 1)
        lmax = fmaxf(lmax, __shfl_xor_sync(0xffffffffu, lmax, m));
    if (lane == 0) red[warp] = lmax;
    __syncthreads();
    float bmax = red[0];
    #pragma unroll
    for (int w = 1; w < 8; w++) bmax = fmaxf(bmax, red[w]);

    float lsum = 0.f;
    for (int t = tid; t < NT; t += 256) {
        const float e = __expf(s[t] - bmax);
        s[t] = e;
        lsum += e;
    }
    #pragma unroll
    for (int m = 16; m; m >>= 1)
        lsum += __shfl_xor_sync(0xffffffffu, lsum, m);
    __syncthreads();
    if (lane == 0) red[warp] = lsum;
    __syncthreads();
    float bsum = 0.f;
    #pragma unroll
    for (int w = 0; w < 8; w++) bsum += red[w];
    const float inv = 1.f / bsum;
    for (int t = tid; t < NT; t += 256)
        out_w[b * NT + t] = s[t] * inv;
}

// ====== Kernel D: context partials (16-way t-split, LDG.64 vectorized) =====
// grid (NB, CTX_SPLIT); 256 threads; each thread owns 4 units (uint2 = 4 fp16)
__global__ void __launch_bounds__(256) context_part_kernel(
    const float* __restrict__ w) {
    __shared__ float ws[T_SLICE];       // 128
    const int b  = blockIdx.x;
    const int tc = blockIdx.y;
    const int t0 = tc * T_SLICE;
    if (threadIdx.x < T_SLICE)
        ws[threadIdx.x] = w[b * NT + t0 + threadIdx.x];
    __syncthreads();
    const int u = threadIdx.x * 4;
    const __half* xp = g_xh + (size_t)b * NT * UNITS + (size_t)t0 * UNITS + u;

    float a0 = 0.f, a1 = 0.f, a2 = 0.f, a3 = 0.f;
    float b0 = 0.f, b1 = 0.f, b2 = 0.f, b3 = 0.f;
    #pragma unroll 2
    for (int t = 0; t < T_SLICE; t += 2) {
        const uint2 p0 = *(const uint2*)(xp + (size_t)t * UNITS);
        const uint2 p1 = *(const uint2*)(xp + (size_t)(t + 1) * UNITS);
        const float w0 = ws[t], w1 = ws[t + 1];
        const float2 f00 = __half22float2(*(const __half2*)&p0.x);
        const float2 f01 = __half22float2(*(const __half2*)&p0.y);
        const float2 f10 = __half22float2(*(const __half2*)&p1.x);
        const float2 f11 = __half22float2(*(const __half2*)&p1.y);
        a0 += w0 * f00.x; a1 += w0 * f00.y;
        a2 += w0 * f01.x; a3 += w0 * f01.y;
        b0 += w1 * f10.x; b1 += w1 * f10.y;
        b2 += w1 * f11.x; b3 += w1 * f11.y;
    }
    float4 r;
    r.x = a0 + b0; r.y = a1 + b1; r.z = a2 + b2; r.w = a3 + b3;
    *(float4*)(g_ctxp + (size_t)tc * NB * UNITS + b * UNITS + u) = r;
}

__global__ void context_reduce_kernel(float* __restrict__ out_ctx) {
    const int i = blockIdx.x * 256 + threadIdx.x;
    float s = 0.f;
    #pragma unroll
    for (int p = 0; p < CTX_SPLIT; ++p)
        s += g_ctxp[(size_t)p * NB * UNITS + i];
    out_ctx[i] = s;
}

// ---------------------------------------------------------------------------
extern "C" void kernel_launch(void* const* d_in, const int* in_sizes, int n_in,
                              void* d_out, int out_size) {
    const float* x      = (const float*)d_in[0];
    const float* hidden = (const float*)d_in[1];
    const float* W1_w   = (const float*)d_in[2];
    const float* W1_b   = (const float*)d_in[3];
    const float* W2_w   = (const float*)d_in[4];
    const float* W2_b   = (const float*)d_in[5];
    const float* V_w    = (const float*)d_in[6];
    // d_in[7] = V_b: softmax-invariant, unused.

    float* out     = (float*)d_out;
    float* out_ctx = out;                   // 32*1024
    float* out_w   = out + NB * UNITS;      // 32*2048

    cudaFuncSetAttribute(score_kernel,
                         cudaFuncAttributeMaxDynamicSharedMemorySize, S_TOTAL);

    prep_kernel<<<XBLOCKS + WBLOCKS + BBLOCKS, 256>>>(x, W1_w, hidden,
                                                      W2_w, W1_b, W2_b);
    score_kernel<<<GRID_P, 512, S_TOTAL>>>(V_w);
    softmax_kernel<<<NB, 256>>>(out_w);
    context_part_kernel<<<dim3(NB, CTX_SPLIT), 256>>>(out_w);
    context_reduce_kernel<<<NB * UNITS / 256, 256>>>(out_ctx);
}